// round 10
// baseline (speedup 1.0000x reference)
#include <cuda_runtime.h>
#include <math.h>

#define B_ 2
#define M_ 384
#define N_ 384

// Shared-memory layout (float offsets)
#define OFF_S     0        // 8 copies * 640 = 5120
#define OFF_CW    5120     // 384 * float4 corner weights = 1536
#define OFF_CPK   6656     // 384 ints (n<<8 | y0<<4 | (x0+1))
#define OFF_STOT  7040     // 640
#define OFF_SFOLD 7680     // 512  [t(8)][w(4)][comp(16)]
#define OFF_RED   8192     // 8 (psi warp partials)
#define OFF_PSI   8200     // 1
#define SMEM_FLOATS 8204
#define SMEM_BYTES  (SMEM_FLOATS * 4)   // 32816 B -> 6 blocks/SM

__global__ __launch_bounds__(256, 6)
void equi_cts_conv_kernel(const float* __restrict__ field,
                          const float* __restrict__ center,
                          const float* __restrict__ feat,
                          const float* __restrict__ mask,
                          const float* __restrict__ kern,
                          float* __restrict__ out)
{
    extern __shared__ float sm[];
    float*  S     = sm + OFF_S;
    float4* cw4   = (float4*)(sm + OFF_CW);
    int*    cpk   = (int*)(sm + OFF_CPK);
    float*  Stot  = sm + OFF_STOT;
    float*  Sfold = sm + OFF_SFOLD;
    float*  red   = sm + OFF_RED;
    float*  shpsi = sm + OFF_PSI;
    __shared__ int wcnt[16];

    const int tid  = threadIdx.x;
    const int lane = tid & 31;
    const int warp = tid >> 5;
    const int bm   = blockIdx.x;
    const int b    = bm / M_;

    const float cx = center[bm * 2 + 0];
    const float cy = center[bm * 2 + 1];

    // ---------- Phase 0: zero S copies ----------
    {
        float4 z = make_float4(0.f, 0.f, 0.f, 0.f);
        float4* S4 = (float4*)S;
        #pragma unroll
        for (int i = tid; i < 1280; i += 256) S4[i] = z;
    }

    // ---------- Phase A1: geometry + corner weights + ballots ----------
    float psi_part = 0.f;
    unsigned ballots[2];
    float4 a_cw[2];
    int    a_pk[2];
    bool   a_act[2];
    #pragma unroll
    for (int r = 0; r < 2; ++r) {
        int n = r * 256 + tid;
        bool act = false;
        float4 cwv = make_float4(0.f, 0.f, 0.f, 0.f);
        int pack = 0;
        if (n < N_) {
            float2 fp = *(const float2*)(field + ((size_t)b * N_ + n) * 2);
            float relx = (fp.x - cx) * (1.0f / 1.5f);
            float rely = (fp.y - cy) * (1.0f / 1.5f);
            float r2 = relx * relx + rely * rely;
            float s  = 1.0f - r2;
            if (s > 0.0f) {
                float att = s * s * s * mask[(size_t)b * N_ + n];
                float rr = sqrtf(r2 + 1e-9f);
                // ---- theta/pi via octant-reduced poly (replaces atan2f) ----
                float ax = fabsf(relx), ay = fabsf(rely);
                float mx = fmaxf(ax, ay), mn = fminf(ax, ay);
                float z  = (mx > 0.0f) ? __fdividef(mn, mx) : 0.0f;
                float z2 = z * z;
                float q = -0.0037310f;
                q = fmaf(q, z2,  0.0167600f);
                q = fmaf(q, z2, -0.0370620f);
                q = fmaf(q, z2,  0.0616061f);
                q = fmaf(q, z2, -0.1058772f);
                q = fmaf(q, z2,  0.3183026478f);
                q = q * z;                          // atan(z)/pi
                if (ay > ax)       q = 0.5f - q;
                if (relx < 0.0f)   q = 1.0f - q;
                q = copysignf(q, rely);             // theta/pi in [-1,1]
                // ------------------------------------------------------------
                float ix = 4.0f * rr - 0.5f;        // ((gx+1)*W-1)/2, W=4
                float iy = fmaf(4.0f, q, 4.5f);     // 4.5 + 5*(0.8*q), H=10
                float x0f = floorf(ix), y0f = floorf(iy);
                float wx = ix - x0f;
                float wy = iy - y0f;
                int x0 = (int)x0f, y0 = (int)y0f;   // x0 in [-1,3], y0 in [0,8]
                float omx = 1.0f - wx, omy = 1.0f - wy;
                cwv.x = att * omx * omy;
                cwv.y = att * wx  * omy;
                cwv.z = att * omx * wy;
                cwv.w = att * wx  * wy;
                pack = ((x0 + 1) | (y0 << 4)) | (n << 8);
                psi_part += att;
                act = (att != 0.0f);
            }
        }
        a_cw[r] = cwv; a_pk[r] = pack; a_act[r] = act;
        ballots[r] = __ballot_sync(0xffffffffu, act);
        if (lane == 0) wcnt[r * 8 + warp] = __popc(ballots[r]);
    }

    // psi warp-reduce
    #pragma unroll
    for (int o = 16; o; o >>= 1) psi_part += __shfl_xor_sync(0xffffffffu, psi_part, o);
    if (lane == 0) red[warp] = psi_part;
    __syncthreads();   // covers S-zeroing, wcnt, red

    // ---------- Phase A2: deterministic prefix + compacted write ----------
    int nact;
    {
        int tot = 0, base0 = 0, base1 = 0;
        #pragma unroll
        for (int s2 = 0; s2 < 16; ++s2) {
            if (s2 == warp)     base0 = tot;
            if (s2 == warp + 8) base1 = tot;
            tot += wcnt[s2];
        }
        nact = tot;
        unsigned lt = (1u << lane) - 1u;
        if (a_act[0]) {
            int idx = base0 + __popc(ballots[0] & lt);
            cw4[idx] = a_cw[0]; cpk[idx] = a_pk[0];
        }
        if (a_act[1]) {
            int idx = base1 + __popc(ballots[1] & lt);
            cw4[idx] = a_cw[1]; cpk[idx] = a_pk[1];
        }
        if (tid == 0) {
            float p = 0.f;
            #pragma unroll
            for (int w = 0; w < 8; ++w) p += red[w];
            shpsi[0] = (p == 0.0f) ? 1.0f : p;
        }
    }
    __syncthreads();

    // ---------- Phase B: scatter, pipelined x2 for LDG MLP ----------
    // lane = corner(2b)*8 + pairi(3b). Corners of one n hit 4 distinct cells;
    // half-warp LDS.64 phases are bank-conflict-free for cell stride 16.
    // Dynamic smem indices keep RMW1/RMW2 ordered (may-alias).
    {
        const int corner = lane >> 3;
        const int pairi  = lane & 7;
        const int cbx = corner & 1;
        const int cby = corner >> 1;
        float* Smine = S + warp * 640;
        const float* cwf = (const float*)cw4;
        const float* featB = feat + (size_t)b * N_ * 16;

        int k = warp;
        for (; k + 8 < nact; k += 16) {
            float A1 = cwf[k * 4 + corner];
            float A2 = cwf[(k + 8) * 4 + corner];
            int pk1 = cpk[k];
            int pk2 = cpk[k + 8];
            int xi1 = (pk1 & 15) - 1 + cbx, yi1 = ((pk1 >> 4) & 15) + cby;
            int xi2 = (pk2 & 15) - 1 + cbx, yi2 = ((pk2 >> 4) & 15) + cby;
            A1 = ((unsigned)xi1 <= 3u) ? A1 : 0.0f;  xi1 &= 3;
            A2 = ((unsigned)xi2 <= 3u) ? A2 : 0.0f;  xi2 &= 3;
            float2 f1 = __ldg((const float2*)(featB + ((pk1 >> 4) & ~15) + pairi * 2));
            float2 f2 = __ldg((const float2*)(featB + ((pk2 >> 4) & ~15) + pairi * 2));
            float* sp1 = Smine + (yi1 * 4 + xi1) * 16 + pairi * 2;
            float2 sv1 = *(float2*)sp1;
            sv1.x = fmaf(A1, f1.x, sv1.x);
            sv1.y = fmaf(A1, f1.y, sv1.y);
            *(float2*)sp1 = sv1;
            float* sp2 = Smine + (yi2 * 4 + xi2) * 16 + pairi * 2;
            float2 sv2 = *(float2*)sp2;
            sv2.x = fmaf(A2, f2.x, sv2.x);
            sv2.y = fmaf(A2, f2.y, sv2.y);
            *(float2*)sp2 = sv2;
        }
        if (k < nact) {
            float A = cwf[k * 4 + corner];
            int pk = cpk[k];
            int xi = (pk & 15) - 1 + cbx, yi = ((pk >> 4) & 15) + cby;
            A = ((unsigned)xi <= 3u) ? A : 0.0f;  xi &= 3;
            float2 f = __ldg((const float2*)(featB + ((pk >> 4) & ~15) + pairi * 2));
            float* sp = Smine + (yi * 4 + xi) * 16 + pairi * 2;
            float2 sv = *(float2*)sp;
            sv.x = fmaf(A, f.x, sv.x);
            sv.y = fmaf(A, f.y, sv.y);
            *(float2*)sp = sv;
        }
    }
    __syncthreads();

    // ---------- Phase C1: reduce 8 S copies (float4) ----------
    {
        const float4* S4 = (const float4*)S;
        float4* Stot4 = (float4*)Stot;
        for (int e = tid; e < 160; e += 256) {
            float4 a = S4[e];
            #pragma unroll
            for (int c = 1; c < 8; ++c) {
                float4 v = S4[c * 160 + e];
                a.x += v.x; a.y += v.y; a.z += v.z; a.w += v.w;
            }
            Stot4[e] = a;
        }
    }
    __syncthreads();

    // ---------- Phase C2a: fold theta-wrap, layout [t(8)][w(4)][comp(16)] ----------
    {
        const float4* Stot4 = (const float4*)Stot;
        float4* Sfold4 = (float4*)Sfold;
        for (int e = tid; e < 128; e += 256) {
            int c4 = e & 3;
            int w  = (e >> 2) & 3;
            int t  = e >> 4;
            float4 v = Stot4[((t + 1) * 4 + w) * 4 + c4];       // h = t+1 (1..8)
            if (t == 7) {
                float4 u = Stot4[(0 * 4 + w) * 4 + c4];         // h = 0
                v.x += u.x; v.y += u.y; v.z += u.z; v.w += u.w;
            }
            if (t == 0) {
                float4 u = Stot4[(9 * 4 + w) * 4 + c4];         // h = 9
                v.x += u.x; v.y += u.y; v.z += u.z; v.w += u.w;
            }
            Sfold4[e] = v;
        }
    }
    __syncthreads();

    // ---------- Phase C2b: out[o,y] = sum kern[o,i,w,t,y,x] * Sfold[t,w,i,x] ----------
    // warp = o; lane = w*8 + i. kern: 8x LDG.128 per lane (L1-resident).
    // Sfold: LDS.64 at (t*4+w)*16 + i*2 -> half-warp phases conflict-free.
    {
        const int w = lane >> 3;
        const int i = lane & 7;
        const float4* kb4 = (const float4*)(kern + warp * 1024 + i * 128 + w * 32);
        const float2* Sf2 = (const float2*)Sfold;
        float acc0 = 0.f, acc1 = 0.f;
        #pragma unroll
        for (int t = 0; t < 8; ++t) {
            float4 kv = __ldg(kb4 + t);                 // (t, y0x0, y0x1, y1x0, y1x1)
            float2 sf = Sf2[(t * 4 + w) * 8 + i];       // (x0, x1)
            acc0 = fmaf(kv.x, sf.x, fmaf(kv.y, sf.y, acc0));
            acc1 = fmaf(kv.z, sf.x, fmaf(kv.w, sf.y, acc1));
        }
        #pragma unroll
        for (int o = 16; o; o >>= 1) {
            acc0 += __shfl_xor_sync(0xffffffffu, acc0, o);
            acc1 += __shfl_xor_sync(0xffffffffu, acc1, o);
        }
        if (lane == 0) {
            float inv = 1.0f / shpsi[0];
            *(float2*)(out + bm * 16 + warp * 2) = make_float2(acc0 * inv, acc1 * inv);
        }
    }
}

extern "C" void kernel_launch(void* const* d_in, const int* in_sizes, int n_in,
                              void* d_out, int out_size)
{
    const float* field  = (const float*)d_in[0];
    const float* center = (const float*)d_in[1];
    const float* feat   = (const float*)d_in[2];
    const float* mask   = (const float*)d_in[3];
    const float* kern   = (const float*)d_in[4];
    float* out = (float*)d_out;

    cudaFuncSetAttribute(equi_cts_conv_kernel,
                         cudaFuncAttributeMaxDynamicSharedMemorySize, SMEM_BYTES);
    equi_cts_conv_kernel<<<B_ * M_, 256, SMEM_BYTES>>>(field, center, feat, mask, kern, out);
}